// round 1
// baseline (speedup 1.0000x reference)
#include <cuda_runtime.h>
#include <math.h>

#define BATCH 8
#define NDIM 256
#define TDIM 64
#define FDIM 33                    // rFFT bins for length-64 real input
#define SLICE (NDIM * NDIM)        // 65536
#define NBF (BATCH * FDIM)         // 264
#define TOTAL_TUBES (BATCH * NDIM * NDIM)  // 524288
#define PLANE_ELEMS ((size_t)NBF * SLICE)  // 17,301,504 floats

// ---------------- scratch (device globals: allocation-free) ----------------
__device__ float g_Afr[PLANE_ELEMS];
__device__ float g_Afi[PLANE_ELEMS];
__device__ float g_Bfr[PLANE_ELEMS];
__device__ float g_Bfi[PLANE_ELEMS];
__device__ float g_Cfr[PLANE_ELEMS];
__device__ float g_Cfi[PLANE_ELEMS];

// twiddle tables
__device__ float g_cos[FDIM * TDIM];    // cos(2*pi*f*t/64)
__device__ float g_sin[FDIM * TDIM];    // sin(2*pi*f*t/64)
// inverse tables, transposed [t][f_padded], f padded 33 -> 36, weights folded
#define FPAD 36
__device__ float g_icosT[TDIM * FPAD];
__device__ float g_isinT[TDIM * FPAD];

__global__ void init_twiddles() {
    int idx = blockIdx.x * blockDim.x + threadIdx.x;
    if (idx < FDIM * TDIM) {
        int f = idx / TDIM, t = idx % TDIM;
        int r = (f * t) & 63;
        double s, c;
        sincospi(2.0 * (double)r / 64.0, &s, &c);
        g_cos[idx] = (float)c;
        g_sin[idx] = (float)s;
    }
    if (idx < TDIM * FPAD) {
        int t = idx / FPAD, f = idx % FPAD;
        float vc = 0.f, vs = 0.f;
        if (f < FDIM) {
            int r = (f * t) & 63;
            double s, c;
            sincospi(2.0 * (double)r / 64.0, &s, &c);
            double w = (f == 0 || f == 32) ? 1.0 : 2.0;
            vc = (float)(w * c / 64.0);
            vs = (float)(w * s / 64.0);
        }
        g_icosT[idx] = vc;
        g_isinT[idx] = vs;
    }
}

// ---------------- forward rDFT: tubes -> split-complex [b][f][row][col] ----
// One thread = one tube (64 reals in registers). 64 tubes per block.
__global__ void __launch_bounds__(64) dft_fwd(const float* __restrict__ x,
                                              float* __restrict__ outr,
                                              float* __restrict__ outi) {
    __shared__ float s[64 * 68];            // padded stride 68 (16B aligned rows)
    __shared__ float cs[FDIM * TDIM];
    __shared__ float ss[FDIM * TDIM];
    int tid = threadIdx.x;
    size_t tube_base = (size_t)blockIdx.x * 64;
    const float* src = x + tube_base * TDIM;

    // coalesced stage of 64 contiguous tubes (16 KB)
    for (int idx = tid; idx < 64 * TDIM; idx += 64)
        s[(idx >> 6) * 68 + (idx & 63)] = src[idx];
    for (int idx = tid; idx < FDIM * TDIM; idx += 64) {
        cs[idx] = g_cos[idx];
        ss[idx] = g_sin[idx];
    }
    __syncthreads();

    // own tube -> registers
    float v[64];
    const float* srow = &s[tid * 68];
#pragma unroll
    for (int q = 0; q < 16; q++) {
        float4 tmp = *(const float4*)&srow[q * 4];
        v[q * 4 + 0] = tmp.x; v[q * 4 + 1] = tmp.y;
        v[q * 4 + 2] = tmp.z; v[q * 4 + 3] = tmp.w;
    }

    size_t tb = tube_base + tid;
    int b = (int)(tb >> 16);
    int rc = (int)(tb & 65535);
    size_t obase = (size_t)b * FDIM * SLICE + rc;

    for (int f = 0; f < FDIM; f++) {
        const float4* c4 = (const float4*)&cs[f * TDIM];
        const float4* s4 = (const float4*)&ss[f * TDIM];
        float re0 = 0.f, re1 = 0.f, im0 = 0.f, im1 = 0.f;
#pragma unroll
        for (int q = 0; q < 16; q++) {
            float4 c = c4[q];
            float4 sn = s4[q];
            re0 = fmaf(v[q * 4 + 0], c.x, re0);
            im0 = fmaf(v[q * 4 + 0], sn.x, im0);
            re1 = fmaf(v[q * 4 + 1], c.y, re1);
            im1 = fmaf(v[q * 4 + 1], sn.y, im1);
            re0 = fmaf(v[q * 4 + 2], c.z, re0);
            im0 = fmaf(v[q * 4 + 2], sn.z, im0);
            re1 = fmaf(v[q * 4 + 3], c.w, re1);
            im1 = fmaf(v[q * 4 + 3], sn.w, im1);
        }
        outr[obase + (size_t)f * SLICE] = re0 + re1;
        outi[obase + (size_t)f * SLICE] = -(im0 + im1);   // e^{-i theta}
    }
}

// ---------------- batched complex GEMM per (b,f): C = A * B ---------------
// grid (4,4,264), block 256. 64x64 output tile per block, 4x4 per thread.
__global__ void __launch_bounds__(256) cgemm(const float* __restrict__ Ar,
                                             const float* __restrict__ Ai,
                                             const float* __restrict__ Br,
                                             const float* __restrict__ Bi,
                                             float* __restrict__ Cr,
                                             float* __restrict__ Ci) {
    __shared__ float sAr[16 * 68], sAi[16 * 68];   // [k][m], padded
    __shared__ float sBr[16 * 64], sBi[16 * 64];   // [k][n]
    size_t off = (size_t)blockIdx.z * SLICE;
    Ar += off; Ai += off; Br += off; Bi += off; Cr += off; Ci += off;
    int i0 = blockIdx.y * 64, n0 = blockIdx.x * 64;
    int tid = threadIdx.x;
    int tx = tid & 15, ty = tid >> 4;

    float cr[4][4] = {}, ci[4][4] = {};

    for (int k0 = 0; k0 < NDIM; k0 += 16) {
        for (int idx = tid; idx < 64 * 16; idx += 256) {
            int kk = idx & 15, m = idx >> 4;
            int g = (i0 + m) * NDIM + k0 + kk;
            sAr[kk * 68 + m] = Ar[g];
            sAi[kk * 68 + m] = Ai[g];
        }
        for (int idx = tid; idx < 16 * 64; idx += 256) {
            int n = idx & 63, kk = idx >> 6;
            int g = (k0 + kk) * NDIM + n0 + n;
            sBr[kk * 64 + n] = Br[g];
            sBi[kk * 64 + n] = Bi[g];
        }
        __syncthreads();
#pragma unroll
        for (int kk = 0; kk < 16; kk++) {
            float4 arv = *(const float4*)&sAr[kk * 68 + ty * 4];
            float4 aiv = *(const float4*)&sAi[kk * 68 + ty * 4];
            float4 brv = *(const float4*)&sBr[kk * 64 + tx * 4];
            float4 biv = *(const float4*)&sBi[kk * 64 + tx * 4];
            float ar[4] = {arv.x, arv.y, arv.z, arv.w};
            float ai[4] = {aiv.x, aiv.y, aiv.z, aiv.w};
            float br[4] = {brv.x, brv.y, brv.z, brv.w};
            float bi[4] = {biv.x, biv.y, biv.z, biv.w};
#pragma unroll
            for (int m = 0; m < 4; m++) {
#pragma unroll
                for (int n = 0; n < 4; n++) {
                    cr[m][n] = fmaf(ar[m], br[n], cr[m][n]);
                    cr[m][n] = fmaf(-ai[m], bi[n], cr[m][n]);
                    ci[m][n] = fmaf(ar[m], bi[n], ci[m][n]);
                    ci[m][n] = fmaf(ai[m], br[n], ci[m][n]);
                }
            }
        }
        __syncthreads();
    }

#pragma unroll
    for (int m = 0; m < 4; m++) {
        int row = (i0 + ty * 4 + m) * NDIM + n0 + tx * 4;
        *(float4*)&Cr[row] = make_float4(cr[m][0], cr[m][1], cr[m][2], cr[m][3]);
        *(float4*)&Ci[row] = make_float4(ci[m][0], ci[m][1], ci[m][2], ci[m][3]);
    }
}

// ---------------- inverse rDFT: split-complex [b][f][i][n] -> real tubes ---
__global__ void __launch_bounds__(64) dft_inv(const float* __restrict__ cfr_g,
                                              const float* __restrict__ cfi_g,
                                              float* __restrict__ out) {
    __shared__ float cf[2 * FDIM * 64];        // [re|im][f][n]
    __shared__ float tc[TDIM * FPAD];          // icos transposed [t][f]
    __shared__ float ts[TDIM * FPAD];          // isin transposed [t][f]
    int tid = threadIdx.x;
    size_t tube_base = (size_t)blockIdx.x * 64;
    int b = (int)(tube_base >> 16);
    int rc0 = (int)(tube_base & 65535);        // i*256 + n0
    size_t gbase = (size_t)b * FDIM * SLICE + rc0;

    for (int idx = tid; idx < FDIM * 64; idx += 64) {
        int f = idx >> 6, n = idx & 63;
        size_t g = gbase + (size_t)f * SLICE + n;
        cf[idx] = cfr_g[g];
        cf[FDIM * 64 + idx] = cfi_g[g];
    }
    for (int idx = tid; idx < TDIM * FPAD; idx += 64) {
        tc[idx] = g_icosT[idx];
        ts[idx] = g_isinT[idx];
    }
    __syncthreads();

    // this thread's 33 spectrum values (n = tid), pad to 36 with zeros
    float cr[FPAD], cim[FPAD];
#pragma unroll
    for (int f = 0; f < FDIM; f++) {
        cr[f]  = cf[f * 64 + tid];
        cim[f] = cf[FDIM * 64 + f * 64 + tid];
    }
#pragma unroll
    for (int f = FDIM; f < FPAD; f++) { cr[f] = 0.f; cim[f] = 0.f; }

    float* dst = out + (tube_base + tid) * TDIM;
    for (int t4 = 0; t4 < 16; t4++) {
        float4 res;
        float* rp = &res.x;
#pragma unroll
        for (int e = 0; e < 4; e++) {
            int t = t4 * 4 + e;
            const float4* c4 = (const float4*)&tc[t * FPAD];
            const float4* s4 = (const float4*)&ts[t * FPAD];
            float a0 = 0.f, a1 = 0.f, a2 = 0.f, a3 = 0.f;
#pragma unroll
            for (int fq = 0; fq < FPAD / 4; fq++) {
                float4 c = c4[fq];
                float4 s = s4[fq];
                a0 = fmaf(cr[fq * 4 + 0], c.x, a0);
                a1 = fmaf(cim[fq * 4 + 0], s.x, a1);
                a2 = fmaf(cr[fq * 4 + 1], c.y, a2);
                a3 = fmaf(cim[fq * 4 + 1], s.y, a3);
                a0 = fmaf(cr[fq * 4 + 2], c.z, a0);
                a1 = fmaf(cim[fq * 4 + 2], s.z, a1);
                a2 = fmaf(cr[fq * 4 + 3], c.w, a2);
                a3 = fmaf(cim[fq * 4 + 3], s.w, a3);
            }
            rp[e] = (a0 + a2) - (a1 + a3);
        }
        *(float4*)&dst[t4 * 4] = res;
    }
}

// ---------------------------------------------------------------------------
extern "C" void kernel_launch(void* const* d_in, const int* in_sizes, int n_in,
                              void* d_out, int out_size) {
    (void)in_sizes; (void)n_in; (void)out_size;
    const float* A = (const float*)d_in[0];
    const float* B = (const float*)d_in[1];
    float* C = (float*)d_out;

    float *afr, *afi, *bfr, *bfi, *cfr, *cfi;
    cudaGetSymbolAddress((void**)&afr, g_Afr);
    cudaGetSymbolAddress((void**)&afi, g_Afi);
    cudaGetSymbolAddress((void**)&bfr, g_Bfr);
    cudaGetSymbolAddress((void**)&bfi, g_Bfi);
    cudaGetSymbolAddress((void**)&cfr, g_Cfr);
    cudaGetSymbolAddress((void**)&cfi, g_Cfi);

    init_twiddles<<<(TDIM * FPAD + 255) / 256, 256>>>();
    dft_fwd<<<TOTAL_TUBES / 64, 64>>>(A, afr, afi);
    dft_fwd<<<TOTAL_TUBES / 64, 64>>>(B, bfr, bfi);
    cgemm<<<dim3(NDIM / 64, NDIM / 64, NBF), 256>>>(afr, afi, bfr, bfi, cfr, cfi);
    dft_inv<<<TOTAL_TUBES / 64, 64>>>(cfr, cfi, C);
}

// round 4
// speedup vs baseline: 1.3381x; 1.3381x over previous
#include <cuda_runtime.h>
#include <math.h>

#define BATCH 8
#define NDIM 256
#define TDIM 64
#define FDIM 33                    // rFFT bins for length-64 real input
#define SLICE (NDIM * NDIM)        // 65536
#define NBF (BATCH * FDIM)         // 264
#define TOTAL_TUBES (BATCH * NDIM * NDIM)  // 524288
#define PLANE_ELEMS ((size_t)NBF * SLICE)

typedef unsigned long long ull;

// ---------------- f32x2 packed helpers (Blackwell FFMA2) -------------------
__device__ __forceinline__ void ffma2(ull& d, ull a, ull b) {
    asm("fma.rn.f32x2 %0, %1, %2, %0;" : "+l"(d) : "l"(a), "l"(b));
}
__device__ __forceinline__ ull bcast2(float x) {
    ull r; asm("mov.b64 %0, {%1, %1};" : "=l"(r) : "f"(x)); return r;
}
__device__ __forceinline__ ull pack2(float x, float y) {
    ull r; asm("mov.b64 %0, {%1, %2};" : "=l"(r) : "f"(x), "f"(y)); return r;
}
__device__ __forceinline__ float2 unpack2(ull v) {
    float2 f; asm("mov.b64 {%0, %1}, %2;" : "=f"(f.x), "=f"(f.y) : "l"(v)); return f;
}

// ---------------- scratch (device globals: allocation-free) ----------------
__device__ float g_Afr[PLANE_ELEMS];
__device__ float g_Afi[PLANE_ELEMS];
__device__ float g_Bfr[PLANE_ELEMS];
__device__ float g_Bfi[PLANE_ELEMS];
__device__ float g_Cfr[PLANE_ELEMS];
__device__ float g_Cfi[PLANE_ELEMS];

// twiddle tables
__device__ float g_cos[FDIM * TDIM];    // cos(2*pi*f*t/64)
__device__ float g_sin[FDIM * TDIM];    // sin(2*pi*f*t/64)
#define FPAD 36
__device__ float g_icosT[TDIM * FPAD];  //  w*cos/64, [t][f]
__device__ float g_isinT[TDIM * FPAD];  // -w*sin/64 (sign folded)

__global__ void init_twiddles() {
    int idx = blockIdx.x * blockDim.x + threadIdx.x;
    if (idx < FDIM * TDIM) {
        int f = idx / TDIM, t = idx % TDIM;
        int r = (f * t) & 63;
        double s, c;
        sincospi(2.0 * (double)r / 64.0, &s, &c);
        g_cos[idx] = (float)c;
        g_sin[idx] = (float)s;
    }
    if (idx < TDIM * FPAD) {
        int t = idx / FPAD, f = idx % FPAD;
        float vc = 0.f, vs = 0.f;
        if (f < FDIM) {
            int r = (f * t) & 63;
            double s, c;
            sincospi(2.0 * (double)r / 64.0, &s, &c);
            double w = (f == 0 || f == 32) ? 1.0 : 2.0;
            vc = (float)(w * c / 64.0);
            vs = (float)(-w * s / 64.0);
        }
        g_icosT[idx] = vc;
        g_isinT[idx] = vs;
    }
}

// ---------------- forward rDFT: tubes -> split-complex [b][f][row][col] ----
__global__ void __launch_bounds__(64) dft_fwd(const float* __restrict__ x,
                                              float* __restrict__ outr,
                                              float* __restrict__ outi) {
    __shared__ float s[64 * 68];            // stride 68 words (272B, 16B aligned)
    __shared__ float cs[FDIM * TDIM];
    __shared__ float ss[FDIM * TDIM];
    int tid = threadIdx.x;
    size_t tube_base = (size_t)blockIdx.x * 64;
    const float* src = x + tube_base * TDIM;

    for (int idx = tid; idx < 64 * TDIM; idx += 64)
        s[(idx >> 6) * 68 + (idx & 63)] = src[idx];
    for (int idx = tid; idx < FDIM * TDIM; idx += 64) {
        cs[idx] = g_cos[idx];
        ss[idx] = g_sin[idx];
    }
    __syncthreads();

    // own tube -> packed register pairs (pairs along t)
    ull v2[32];
    {
        const ulonglong2* srow = (const ulonglong2*)&s[tid * 68];
#pragma unroll
        for (int q = 0; q < 16; q++) {
            ulonglong2 t = srow[q];
            v2[q * 2] = t.x; v2[q * 2 + 1] = t.y;
        }
    }

    size_t tb = tube_base + tid;
    int b = (int)(tb >> 16);
    int rc = (int)(tb & 65535);
    size_t obase = (size_t)b * FDIM * SLICE + rc;

    for (int f = 0; f < FDIM; f++) {
        const ulonglong2* c4 = (const ulonglong2*)&cs[f * TDIM];
        const ulonglong2* s4 = (const ulonglong2*)&ss[f * TDIM];
        ull rea = 0, reb = 0, ima = 0, imb = 0;
#pragma unroll
        for (int q = 0; q < 16; q++) {
            ulonglong2 c = c4[q];
            ulonglong2 sn = s4[q];
            ffma2(rea, v2[q * 2], c.x);
            ffma2(ima, v2[q * 2], sn.x);
            ffma2(reb, v2[q * 2 + 1], c.y);
            ffma2(imb, v2[q * 2 + 1], sn.y);
        }
        float2 r0 = unpack2(rea), r1 = unpack2(reb);
        float2 i0 = unpack2(ima), i1 = unpack2(imb);
        outr[obase + (size_t)f * SLICE] = (r0.x + r0.y) + (r1.x + r1.y);
        outi[obase + (size_t)f * SLICE] = -((i0.x + i0.y) + (i1.x + i1.y));
    }
}

// ---------------- batched complex GEMM per (b,f): C = A * B ---------------
// 128x64 block tile, 8m x 4n per thread (m packed in f32x2 pairs), 256 thr.
#define ASTR 132
__global__ void __launch_bounds__(256, 2) cgemm(const float* __restrict__ Ar,
                                                const float* __restrict__ Ai,
                                                const float* __restrict__ Br,
                                                const float* __restrict__ Bi,
                                                float* __restrict__ Cr,
                                                float* __restrict__ Ci) {
    __shared__ float sAr[16 * ASTR], sAi[16 * ASTR], sAn[16 * ASTR]; // [k][m]
    __shared__ float sBr[16 * 64], sBi[16 * 64];                     // [k][n]
    size_t off = (size_t)blockIdx.z * SLICE;
    Ar += off; Ai += off; Br += off; Bi += off; Cr += off; Ci += off;
    int i0 = blockIdx.y * 128, n0 = blockIdx.x * 64;
    int tid = threadIdx.x;
    int tx = tid & 15, ty = tid >> 4;        // n = n0+tx*4, m = i0+ty*8

    ull cr2[4][4], ci2[4][4];
#pragma unroll
    for (int mp = 0; mp < 4; mp++)
#pragma unroll
        for (int n = 0; n < 4; n++) { cr2[mp][n] = 0ull; ci2[mp][n] = 0ull; }

    for (int k0 = 0; k0 < NDIM; k0 += 16) {
        // stage A (128m x 16k), transpose to [k][m], also negated-imag plane
#pragma unroll
        for (int it = 0; it < 8; it++) {
            int idx = tid + it * 256;
            int m = idx >> 4, kk = idx & 15;
            int g = (i0 + m) * NDIM + k0 + kk;
            float vr = Ar[g], vi = Ai[g];
            sAr[kk * ASTR + m] = vr;
            sAi[kk * ASTR + m] = vi;
            sAn[kk * ASTR + m] = -vi;
        }
        // stage B (16k x 64n), direct
#pragma unroll
        for (int it = 0; it < 4; it++) {
            int idx = tid + it * 256;
            int kk = idx >> 6, n = idx & 63;
            int g = (k0 + kk) * NDIM + n0 + n;
            sBr[kk * 64 + n] = Br[g];
            sBi[kk * 64 + n] = Bi[g];
        }
        __syncthreads();
#pragma unroll
        for (int kk = 0; kk < 16; kk++) {
            // A pairs along m (free packing from [k][m] layout)
            const ulonglong2* par = (const ulonglong2*)&sAr[kk * ASTR + ty * 8];
            const ulonglong2* pai = (const ulonglong2*)&sAi[kk * ASTR + ty * 8];
            const ulonglong2* pan = (const ulonglong2*)&sAn[kk * ASTR + ty * 8];
            ulonglong2 arA = par[0], arB = par[1];
            ulonglong2 aiA = pai[0], aiB = pai[1];
            ulonglong2 anA = pan[0], anB = pan[1];
            ull ar_p[4] = {arA.x, arA.y, arB.x, arB.y};
            ull ai_p[4] = {aiA.x, aiA.y, aiB.x, aiB.y};
            ull an_p[4] = {anA.x, anA.y, anB.x, anB.y};
            // B broadcast packs
            float4 brv = *(const float4*)&sBr[kk * 64 + tx * 4];
            float4 biv = *(const float4*)&sBi[kk * 64 + tx * 4];
            ull br2[4] = {bcast2(brv.x), bcast2(brv.y), bcast2(brv.z), bcast2(brv.w)};
            ull bi2[4] = {bcast2(biv.x), bcast2(biv.y), bcast2(biv.z), bcast2(biv.w)};
#pragma unroll
            for (int mp = 0; mp < 4; mp++) {
#pragma unroll
                for (int n = 0; n < 4; n++) {
                    ffma2(cr2[mp][n], ar_p[mp], br2[n]);   // + ar*br
                    ffma2(cr2[mp][n], an_p[mp], bi2[n]);   // - ai*bi
                    ffma2(ci2[mp][n], ar_p[mp], bi2[n]);   // + ar*bi
                    ffma2(ci2[mp][n], ai_p[mp], br2[n]);   // + ai*br
                }
            }
            __syncwarp();
        }
        __syncthreads();
    }

    // epilogue: unpack m-pairs, assemble float4 rows
#pragma unroll
    for (int mp = 0; mp < 4; mp++) {
        float2 r[4], q[4];
#pragma unroll
        for (int n = 0; n < 4; n++) { r[n] = unpack2(cr2[mp][n]); q[n] = unpack2(ci2[mp][n]); }
        int row0 = (i0 + ty * 8 + 2 * mp) * NDIM + n0 + tx * 4;
        *(float4*)&Cr[row0]        = make_float4(r[0].x, r[1].x, r[2].x, r[3].x);
        *(float4*)&Cr[row0 + NDIM] = make_float4(r[0].y, r[1].y, r[2].y, r[3].y);
        *(float4*)&Ci[row0]        = make_float4(q[0].x, q[1].x, q[2].x, q[3].x);
        *(float4*)&Ci[row0 + NDIM] = make_float4(q[0].y, q[1].y, q[2].y, q[3].y);
    }
}

// ---------------- inverse rDFT: split-complex [b][f][i][n] -> real tubes ---
__global__ void __launch_bounds__(64) dft_inv(const float* __restrict__ cfr_g,
                                              const float* __restrict__ cfi_g,
                                              float* __restrict__ out) {
    __shared__ float cf[2 * FDIM * 64];        // [re|im][f][n]
    __shared__ float tc[TDIM * FPAD];          // [t][f]  w*cos/64
    __shared__ float ts[TDIM * FPAD];          // [t][f] -w*sin/64
    int tid = threadIdx.x;
    size_t tube_base = (size_t)blockIdx.x * 64;
    int b = (int)(tube_base >> 16);
    int rc0 = (int)(tube_base & 65535);
    size_t gbase = (size_t)b * FDIM * SLICE + rc0;

    for (int idx = tid; idx < FDIM * 64; idx += 64) {
        int f = idx >> 6, n = idx & 63;
        size_t g = gbase + (size_t)f * SLICE + n;
        cf[idx] = cfr_g[g];
        cf[FDIM * 64 + idx] = cfi_g[g];
    }
    for (int idx = tid; idx < TDIM * FPAD; idx += 64) {
        tc[idx] = g_icosT[idx];
        ts[idx] = g_isinT[idx];
    }
    __syncthreads();

    // spectrum as f-pairs (packed once, reused for 64 t)
    ull cr2[17], ci2[17];
#pragma unroll
    for (int p = 0; p < 16; p++) {
        cr2[p] = pack2(cf[(2 * p) * 64 + tid], cf[(2 * p + 1) * 64 + tid]);
        ci2[p] = pack2(cf[FDIM * 64 + (2 * p) * 64 + tid],
                       cf[FDIM * 64 + (2 * p + 1) * 64 + tid]);
    }
    cr2[16] = pack2(cf[32 * 64 + tid], 0.f);
    ci2[16] = pack2(cf[FDIM * 64 + 32 * 64 + tid], 0.f);

    float* dst = out + (tube_base + tid) * TDIM;
    for (int t4 = 0; t4 < 16; t4++) {
        float4 res;
        float* rp = &res.x;
#pragma unroll
        for (int e = 0; e < 4; e++) {
            int t = t4 * 4 + e;
            const ulonglong2* c4 = (const ulonglong2*)&tc[t * FPAD];
            const ulonglong2* s4 = (const ulonglong2*)&ts[t * FPAD];
            ull ca = 0, cb = 0, sa = 0, sb = 0;
#pragma unroll
            for (int p2 = 0; p2 < 8; p2++) {
                ulonglong2 c = c4[p2];
                ulonglong2 s = s4[p2];
                ffma2(ca, cr2[2 * p2], c.x);
                ffma2(cb, cr2[2 * p2 + 1], c.y);
                ffma2(sa, ci2[2 * p2], s.x);
                ffma2(sb, ci2[2 * p2 + 1], s.y);
            }
            // tail pair: f=32 (+ zero-padded f=33) -> float idx 32,33 = ull idx 16
            ffma2(ca, cr2[16], ((const ull*)&tc[t * FPAD])[16]);
            ffma2(sa, ci2[16], ((const ull*)&ts[t * FPAD])[16]);
            float2 c0 = unpack2(ca), c1 = unpack2(cb);
            float2 s0 = unpack2(sa), s1 = unpack2(sb);
            rp[e] = ((c0.x + c0.y) + (c1.x + c1.y)) + ((s0.x + s0.y) + (s1.x + s1.y));
        }
        *(float4*)&dst[t4 * 4] = res;
    }
}

// ---------------------------------------------------------------------------
extern "C" void kernel_launch(void* const* d_in, const int* in_sizes, int n_in,
                              void* d_out, int out_size) {
    (void)in_sizes; (void)n_in; (void)out_size;
    const float* A = (const float*)d_in[0];
    const float* B = (const float*)d_in[1];
    float* C = (float*)d_out;

    float *afr, *afi, *bfr, *bfi, *cfr, *cfi;
    cudaGetSymbolAddress((void**)&afr, g_Afr);
    cudaGetSymbolAddress((void**)&afi, g_Afi);
    cudaGetSymbolAddress((void**)&bfr, g_Bfr);
    cudaGetSymbolAddress((void**)&bfi, g_Bfi);
    cudaGetSymbolAddress((void**)&cfr, g_Cfr);
    cudaGetSymbolAddress((void**)&cfi, g_Cfi);

    init_twiddles<<<(TDIM * FPAD + 255) / 256, 256>>>();
    dft_fwd<<<TOTAL_TUBES / 64, 64>>>(A, afr, afi);
    dft_fwd<<<TOTAL_TUBES / 64, 64>>>(B, bfr, bfi);
    cgemm<<<dim3(NDIM / 64, NDIM / 128, NBF), 256>>>(afr, afi, bfr, bfi, cfr, cfi);
    dft_inv<<<TOTAL_TUBES / 64, 64>>>(cfr, cfi, C);
}

// round 6
// speedup vs baseline: 1.4542x; 1.0868x over previous
#include <cuda_runtime.h>
#include <math.h>

#define BATCH 8
#define NDIM 256
#define TDIM 64
#define FDIM 33                    // rFFT bins for length-64 real input
#define SLICE (NDIM * NDIM)        // 65536
#define NBF (BATCH * FDIM)         // 264
#define TOTAL_TUBES (BATCH * NDIM * NDIM)  // 524288
#define PLANE_ELEMS ((size_t)NBF * SLICE)

typedef unsigned long long ull;

// ---------------- f32x2 packed helpers (Blackwell FFMA2) -------------------
__device__ __forceinline__ void ffma2(ull& d, ull a, ull b) {
    asm("fma.rn.f32x2 %0, %1, %2, %0;" : "+l"(d) : "l"(a), "l"(b));
}
__device__ __forceinline__ ull bcast2(float x) {
    ull r; asm("mov.b64 %0, {%1, %1};" : "=l"(r) : "f"(x)); return r;
}
__device__ __forceinline__ float2 unpack2(ull v) {
    float2 f; asm("mov.b64 {%0, %1}, %2;" : "=f"(f.x), "=f"(f.y) : "l"(v)); return f;
}

// ---------------- scratch (device globals: allocation-free) ----------------
__device__ float g_Afr[PLANE_ELEMS];
__device__ float g_Afi[PLANE_ELEMS];
__device__ float g_Bfr[PLANE_ELEMS];
__device__ float g_Bfi[PLANE_ELEMS];
__device__ float g_Cfr[PLANE_ELEMS];
__device__ float g_Cfi[PLANE_ELEMS];

// twiddle tables
#define FWF 36                       // padded forward freq count ([t][f] layout)
__device__ float g_cosT[TDIM * FWF];   // [t][f]  cos(2*pi*f*t/64), f<33 else 0
__device__ float g_sinT[TDIM * FWF];   // [t][f] -sin(2*pi*f*t/64)
__device__ float g_icosF[FDIM * TDIM]; // [f][t]  w*cos/64
__device__ float g_isinF[FDIM * TDIM]; // [f][t] -w*sin/64

__global__ void init_twiddles() {
    int idx = blockIdx.x * blockDim.x + threadIdx.x;
    if (idx < TDIM * FWF) {
        int t = idx / FWF, f = idx % FWF;
        float vc = 0.f, vs = 0.f;
        if (f < FDIM) {
            int r = (f * t) & 63;
            double s, c;
            sincospi(2.0 * (double)r / 64.0, &s, &c);
            vc = (float)c;
            vs = (float)(-s);
        }
        g_cosT[idx] = vc;
        g_sinT[idx] = vs;
    }
    if (idx < FDIM * TDIM) {
        int f = idx / TDIM, t = idx % TDIM;
        int r = (f * t) & 63;
        double s, c;
        sincospi(2.0 * (double)r / 64.0, &s, &c);
        double w = (f == 0 || f == 32) ? 1.0 : 2.0;
        g_icosF[idx] = (float)(w * c / 64.0);
        g_isinF[idx] = (float)(-w * s / 64.0);
    }
}

// ---------------- forward rDFT as GEMM: C[f,tube] = W[f,t] V[t,tube] -------
// 64 tubes per block, 128 threads: ty in [0,8) -> 4 freqs, tx in [0,16) -> 4 tubes
__global__ void __launch_bounds__(128) dftf(const float* __restrict__ x,
                                            float* __restrict__ outr,
                                            float* __restrict__ outi) {
    __shared__ float sV[64 * 68];     // [t][tube], pad 68 (272B rows, 16B-aligned)
    __shared__ float sWc[64 * FWF];   // [t][f]
    __shared__ float sWs[64 * FWF];
    int tid = threadIdx.x;
    size_t tube_base = (size_t)blockIdx.x * 64;
    int b = (int)(tube_base >> 16);
    int rc0 = (int)(tube_base & 65535);

    // stage V transposed: 64 tubes x 64 t  (input tube-major)
    {
        const float4* src4 = (const float4*)(x + tube_base * TDIM);
#pragma unroll
        for (int it = 0; it < 8; it++) {
            int flat = tid + it * 128;            // float4 index
            int tube = flat >> 4;
            int t0 = (flat & 15) * 4;
            float4 v = src4[flat];
            sV[(t0 + 0) * 68 + tube] = v.x;
            sV[(t0 + 1) * 68 + tube] = v.y;
            sV[(t0 + 2) * 68 + tube] = v.z;
            sV[(t0 + 3) * 68 + tube] = v.w;
        }
    }
    for (int idx = tid; idx < 64 * FWF; idx += 128) {
        sWc[idx] = g_cosT[idx];
        sWs[idx] = g_sinT[idx];
    }
    __syncthreads();

    int ty = tid >> 4;          // freq group: f = ty*4 .. ty*4+3  (covers 0..31)
    int tx = tid & 15;          // tube group: tube = tx*4 .. +3
    int f0 = ty * 4, tube0 = tx * 4;

    ull accR[4][2], accI[4][2];
#pragma unroll
    for (int ff = 0; ff < 4; ff++) {
        accR[ff][0] = 0; accR[ff][1] = 0; accI[ff][0] = 0; accI[ff][1] = 0;
    }

#pragma unroll 8
    for (int k = 0; k < 64; k++) {
        float4 wc = *(const float4*)&sWc[k * FWF + f0];
        float4 ws = *(const float4*)&sWs[k * FWF + f0];
        ulonglong2 vp = *(const ulonglong2*)&sV[k * 68 + tube0];
        const float* wcp = &wc.x;
        const float* wsp = &ws.x;
#pragma unroll
        for (int ff = 0; ff < 4; ff++) {
            ull bc = bcast2(wcp[ff]);
            ull bs = bcast2(wsp[ff]);
            ffma2(accR[ff][0], vp.x, bc);
            ffma2(accR[ff][1], vp.y, bc);
            ffma2(accI[ff][0], vp.x, bs);
            ffma2(accI[ff][1], vp.y, bs);
        }
    }

    size_t obase = (size_t)b * FDIM * SLICE + rc0;
#pragma unroll
    for (int ff = 0; ff < 4; ff++) {
        int f = f0 + ff;
        float2 r0 = unpack2(accR[ff][0]), r1 = unpack2(accR[ff][1]);
        float2 i0 = unpack2(accI[ff][0]), i1 = unpack2(accI[ff][1]);
        *(float4*)&outr[obase + (size_t)f * SLICE + tube0] =
            make_float4(r0.x, r0.y, r1.x, r1.y);
        *(float4*)&outi[obase + (size_t)f * SLICE + tube0] =
            make_float4(i0.x, i0.y, i1.x, i1.y);
    }

    // f = 32: alternating sum (sin = 0)
    if (tid < 64) {
        float re = 0.f;
#pragma unroll 16
        for (int t = 0; t < 64; t += 2)
            re += sV[t * 68 + tid] - sV[(t + 1) * 68 + tid];
        outr[obase + (size_t)32 * SLICE + tid] = re;
        outi[obase + (size_t)32 * SLICE + tid] = 0.f;
    }
}

// ---------------- batched complex GEMM per (b,f): C = A * B ---------------
// 128x64 block tile, 8m x 4n per thread (m packed in f32x2 pairs), 256 thr.
#define ASTR 132
__global__ void __launch_bounds__(256, 2) cgemm(const float* __restrict__ Ar,
                                                const float* __restrict__ Ai,
                                                const float* __restrict__ Br,
                                                const float* __restrict__ Bi,
                                                float* __restrict__ Cr,
                                                float* __restrict__ Ci) {
    __shared__ float sAr[16 * ASTR], sAi[16 * ASTR], sAn[16 * ASTR]; // [k][m]
    __shared__ float sBr[16 * 64], sBi[16 * 64];                     // [k][n]
    size_t off = (size_t)blockIdx.z * SLICE;
    Ar += off; Ai += off; Br += off; Bi += off; Cr += off; Ci += off;
    int i0 = blockIdx.y * 128, n0 = blockIdx.x * 64;
    int tid = threadIdx.x;
    int tx = tid & 15, ty = tid >> 4;        // n = n0+tx*4, m = i0+ty*8

    ull cr2[4][4], ci2[4][4];
#pragma unroll
    for (int mp = 0; mp < 4; mp++)
#pragma unroll
        for (int n = 0; n < 4; n++) { cr2[mp][n] = 0ull; ci2[mp][n] = 0ull; }

    for (int k0 = 0; k0 < NDIM; k0 += 16) {
        // stage A (128m x 16k), transpose to [k][m], also negated-imag plane
#pragma unroll
        for (int it = 0; it < 8; it++) {
            int idx = tid + it * 256;
            int m = idx >> 4, kk = idx & 15;
            int g = (i0 + m) * NDIM + k0 + kk;
            float vr = Ar[g], vi = Ai[g];
            sAr[kk * ASTR + m] = vr;
            sAi[kk * ASTR + m] = vi;
            sAn[kk * ASTR + m] = -vi;
        }
        // stage B (16k x 64n), direct
#pragma unroll
        for (int it = 0; it < 4; it++) {
            int idx = tid + it * 256;
            int kk = idx >> 6, n = idx & 63;
            int g = (k0 + kk) * NDIM + n0 + n;
            sBr[kk * 64 + n] = Br[g];
            sBi[kk * 64 + n] = Bi[g];
        }
        __syncthreads();
#pragma unroll
        for (int kk = 0; kk < 16; kk++) {
            // A pairs along m (free packing from [k][m] layout)
            const ulonglong2* par = (const ulonglong2*)&sAr[kk * ASTR + ty * 8];
            const ulonglong2* pai = (const ulonglong2*)&sAi[kk * ASTR + ty * 8];
            const ulonglong2* pan = (const ulonglong2*)&sAn[kk * ASTR + ty * 8];
            ulonglong2 arA = par[0], arB = par[1];
            ulonglong2 aiA = pai[0], aiB = pai[1];
            ulonglong2 anA = pan[0], anB = pan[1];
            ull ar_p[4] = {arA.x, arA.y, arB.x, arB.y};
            ull ai_p[4] = {aiA.x, aiA.y, aiB.x, aiB.y};
            ull an_p[4] = {anA.x, anA.y, anB.x, anB.y};
            // B broadcast packs
            float4 brv = *(const float4*)&sBr[kk * 64 + tx * 4];
            float4 biv = *(const float4*)&sBi[kk * 64 + tx * 4];
            ull br2[4] = {bcast2(brv.x), bcast2(brv.y), bcast2(brv.z), bcast2(brv.w)};
            ull bi2[4] = {bcast2(biv.x), bcast2(biv.y), bcast2(biv.z), bcast2(biv.w)};
#pragma unroll
            for (int mp = 0; mp < 4; mp++) {
#pragma unroll
                for (int n = 0; n < 4; n++) {
                    ffma2(cr2[mp][n], ar_p[mp], br2[n]);   // + ar*br
                    ffma2(cr2[mp][n], an_p[mp], bi2[n]);   // - ai*bi
                    ffma2(ci2[mp][n], ar_p[mp], bi2[n]);   // + ar*bi
                    ffma2(ci2[mp][n], ai_p[mp], br2[n]);   // + ai*br
                }
            }
        }
        __syncthreads();
    }

    // epilogue: unpack m-pairs, assemble float4 rows
#pragma unroll
    for (int mp = 0; mp < 4; mp++) {
        float2 r[4], q[4];
#pragma unroll
        for (int n = 0; n < 4; n++) { r[n] = unpack2(cr2[mp][n]); q[n] = unpack2(ci2[mp][n]); }
        int row0 = (i0 + ty * 8 + 2 * mp) * NDIM + n0 + tx * 4;
        *(float4*)&Cr[row0]        = make_float4(r[0].x, r[1].x, r[2].x, r[3].x);
        *(float4*)&Cr[row0 + NDIM] = make_float4(r[0].y, r[1].y, r[2].y, r[3].y);
        *(float4*)&Ci[row0]        = make_float4(q[0].x, q[1].x, q[2].x, q[3].x);
        *(float4*)&Ci[row0 + NDIM] = make_float4(q[0].y, q[1].y, q[2].y, q[3].y);
    }
}

// ---------------- inverse rDFT as GEMM: C[tube,t] = sum_f cr*Tc + ci*Ts ----
// 64 tubes per block, 128 threads: ty in [0,16) -> 4 t, tx in [0,8) -> 8 tubes
__global__ void __launch_bounds__(128) dfti(const float* __restrict__ cfr_g,
                                            const float* __restrict__ cfi_g,
                                            float* __restrict__ out) {
    __shared__ float sCr[FDIM * 64];   // [f][tube]
    __shared__ float sCi[FDIM * 64];
    __shared__ float sTc[FDIM * 64];   // [f][t]  w*cos/64
    __shared__ float sTs[FDIM * 64];   // [f][t] -w*sin/64
    int tid = threadIdx.x;
    size_t tube_base = (size_t)blockIdx.x * 64;
    int b = (int)(tube_base >> 16);
    int rc0 = (int)(tube_base & 65535);
    size_t gbase = (size_t)b * FDIM * SLICE + rc0;

    for (int idx = tid; idx < FDIM * 64; idx += 128) {
        int f = idx >> 6, n = idx & 63;
        size_t g = gbase + (size_t)f * SLICE + n;
        sCr[idx] = cfr_g[g];
        sCi[idx] = cfi_g[g];
        sTc[idx] = g_icosF[idx];
        sTs[idx] = g_isinF[idx];
    }
    __syncthreads();

    int ty = tid >> 3;          // t group: t = ty*4 .. +3
    int tx = tid & 7;           // tube group: tube = tx*8 .. +7
    int t0 = ty * 4, tube0 = tx * 8;

    ull acc[4][4];              // [t][tubepair]
#pragma unroll
    for (int tt = 0; tt < 4; tt++)
#pragma unroll
        for (int p = 0; p < 4; p++) acc[tt][p] = 0ull;

    for (int f = 0; f < FDIM; f++) {
        float4 tc = *(const float4*)&sTc[f * 64 + t0];
        float4 tsv = *(const float4*)&sTs[f * 64 + t0];
        ulonglong2 c01 = *(const ulonglong2*)&sCr[f * 64 + tube0];
        ulonglong2 c23 = *(const ulonglong2*)&sCr[f * 64 + tube0 + 4];
        ulonglong2 i01 = *(const ulonglong2*)&sCi[f * 64 + tube0];
        ulonglong2 i23 = *(const ulonglong2*)&sCi[f * 64 + tube0 + 4];
        ull crp[4] = {c01.x, c01.y, c23.x, c23.y};
        ull cip[4] = {i01.x, i01.y, i23.x, i23.y};
        const float* tcp = &tc.x;
        const float* tsp = &tsv.x;
#pragma unroll
        for (int tt = 0; tt < 4; tt++) {
            ull bc = bcast2(tcp[tt]);
            ull bs = bcast2(tsp[tt]);
#pragma unroll
            for (int p = 0; p < 4; p++) {
                ffma2(acc[tt][p], crp[p], bc);
                ffma2(acc[tt][p], cip[p], bs);
            }
        }
    }

    // write: 8 tubes x 4 consecutive t per thread
    float* dst = out + (tube_base + tube0) * TDIM + t0;
#pragma unroll
    for (int p = 0; p < 4; p++) {
        float2 v0 = unpack2(acc[0][p]);
        float2 v1 = unpack2(acc[1][p]);
        float2 v2 = unpack2(acc[2][p]);
        float2 v3 = unpack2(acc[3][p]);
        *(float4*)&dst[(2 * p) * TDIM]     = make_float4(v0.x, v1.x, v2.x, v3.x);
        *(float4*)&dst[(2 * p + 1) * TDIM] = make_float4(v0.y, v1.y, v2.y, v3.y);
    }
}

// ---------------------------------------------------------------------------
extern "C" void kernel_launch(void* const* d_in, const int* in_sizes, int n_in,
                              void* d_out, int out_size) {
    (void)in_sizes; (void)n_in; (void)out_size;
    const float* A = (const float*)d_in[0];
    const float* B = (const float*)d_in[1];
    float* C = (float*)d_out;

    float *afr, *afi, *bfr, *bfi, *cfr, *cfi;
    cudaGetSymbolAddress((void**)&afr, g_Afr);
    cudaGetSymbolAddress((void**)&afi, g_Afi);
    cudaGetSymbolAddress((void**)&bfr, g_Bfr);
    cudaGetSymbolAddress((void**)&bfi, g_Bfi);
    cudaGetSymbolAddress((void**)&cfr, g_Cfr);
    cudaGetSymbolAddress((void**)&cfi, g_Cfi);

    init_twiddles<<<10, 256>>>();
    dftf<<<TOTAL_TUBES / 64, 128>>>(A, afr, afi);
    dftf<<<TOTAL_TUBES / 64, 128>>>(B, bfr, bfi);
    cgemm<<<dim3(NDIM / 64, NDIM / 128, NBF), 256>>>(afr, afi, bfr, bfi, cfr, cfi);
    dfti<<<TOTAL_TUBES / 64, 128>>>(cfr, cfi, C);
}

// round 11
// speedup vs baseline: 2.3894x; 1.6431x over previous
#include <cuda_runtime.h>
#include <math.h>
#include <stdint.h>

#define BATCH 8
#define NDIM 256
#define TDIM 64
#define FDIM 33                    // rFFT bins for length-64 real input
#define SLICE (NDIM * NDIM)        // 65536
#define NBF (BATCH * FDIM)         // 264
#define TOTAL_TUBES (BATCH * NDIM * NDIM)  // 524288
#define PLANE_ELEMS ((size_t)NBF * SLICE)

typedef unsigned long long ull;

// ---------------- f32x2 packed helpers (Blackwell FFMA2) -------------------
__device__ __forceinline__ void ffma2(ull& d, ull a, ull b) {
    asm("fma.rn.f32x2 %0, %1, %2, %0;" : "+l"(d) : "l"(a), "l"(b));
}
__device__ __forceinline__ ull bcast2(float x) {
    ull r; asm("mov.b64 %0, {%1, %1};" : "=l"(r) : "f"(x)); return r;
}
__device__ __forceinline__ float2 unpack2(ull v) {
    float2 f; asm("mov.b64 {%0, %1}, %2;" : "=f"(f.x), "=f"(f.y) : "l"(v)); return f;
}

// ---------------- tf32 mma.sync helpers (baseline PTX, sm_80+) -------------
__device__ __forceinline__ uint32_t f2tf32(float x) {
    uint32_t r; asm("cvt.rna.tf32.f32 %0, %1;" : "=r"(r) : "f"(x)); return r;
}
__device__ __forceinline__ void mma16n8k8(float* c, const uint32_t* a, const uint32_t* b) {
    asm volatile(
        "mma.sync.aligned.m16n8k8.row.col.f32.tf32.tf32.f32 "
        "{%0,%1,%2,%3}, {%4,%5,%6,%7}, {%8,%9}, {%0,%1,%2,%3};"
        : "+f"(c[0]), "+f"(c[1]), "+f"(c[2]), "+f"(c[3])
        : "r"(a[0]), "r"(a[1]), "r"(a[2]), "r"(a[3]), "r"(b[0]), "r"(b[1]));
}

// ---------------- scratch (device globals: allocation-free) ----------------
__device__ float g_Afr[PLANE_ELEMS];   // [b*f][i][k]
__device__ float g_Afi[PLANE_ELEMS];
__device__ float g_Bfr[PLANE_ELEMS];   // [b*f][n][k]  (transposed)
__device__ float g_Bfi[PLANE_ELEMS];
__device__ float g_Cfr[PLANE_ELEMS];   // [b*f][i][n]
__device__ float g_Cfi[PLANE_ELEMS];

// twiddle tables
#define FWF 36
__device__ float g_cosT[TDIM * FWF];   // [t][f]  cos
__device__ float g_sinT[TDIM * FWF];   // [t][f] -sin
__device__ float g_icosF[FDIM * TDIM]; // [f][t]  w*cos/64
__device__ float g_isinF[FDIM * TDIM]; // [f][t] -w*sin/64

__global__ void init_twiddles() {
    int idx = blockIdx.x * blockDim.x + threadIdx.x;
    if (idx < TDIM * FWF) {
        int t = idx / FWF, f = idx % FWF;
        float vc = 0.f, vs = 0.f;
        if (f < FDIM) {
            int r = (f * t) & 63;
            double s, c;
            sincospi(2.0 * (double)r / 64.0, &s, &c);
            vc = (float)c;
            vs = (float)(-s);
        }
        g_cosT[idx] = vc;
        g_sinT[idx] = vs;
    }
    if (idx < FDIM * TDIM) {
        int f = idx / TDIM, t = idx % TDIM;
        int r = (f * t) & 63;
        double s, c;
        sincospi(2.0 * (double)r / 64.0, &s, &c);
        double w = (f == 0 || f == 32) ? 1.0 : 2.0;
        g_icosF[idx] = (float)(w * c / 64.0);
        g_isinF[idx] = (float)(-w * s / 64.0);
    }
}

// ---------------- forward rDFT (A): tubes -> [b][f][i][k] ------------------
__global__ void __launch_bounds__(128) dftf(const float* __restrict__ x,
                                            float* __restrict__ outr,
                                            float* __restrict__ outi) {
    __shared__ float sV[64 * 68];
    __shared__ float sWc[64 * FWF];
    __shared__ float sWs[64 * FWF];
    int tid = threadIdx.x;
    size_t tube_base = (size_t)blockIdx.x * 64;
    int b = (int)(tube_base >> 16);
    int rc0 = (int)(tube_base & 65535);

    {
        const float4* src4 = (const float4*)(x + tube_base * TDIM);
#pragma unroll
        for (int it = 0; it < 8; it++) {
            int flat = tid + it * 128;
            int tube = flat >> 4;
            int t0 = (flat & 15) * 4;
            float4 v = src4[flat];
            sV[(t0 + 0) * 68 + tube] = v.x;
            sV[(t0 + 1) * 68 + tube] = v.y;
            sV[(t0 + 2) * 68 + tube] = v.z;
            sV[(t0 + 3) * 68 + tube] = v.w;
        }
    }
    for (int idx = tid; idx < 64 * FWF; idx += 128) {
        sWc[idx] = g_cosT[idx];
        sWs[idx] = g_sinT[idx];
    }
    __syncthreads();

    int ty = tid >> 4;
    int tx = tid & 15;
    int f0 = ty * 4, tube0 = tx * 4;

    ull accR[4][2], accI[4][2];
#pragma unroll
    for (int ff = 0; ff < 4; ff++) {
        accR[ff][0] = 0; accR[ff][1] = 0; accI[ff][0] = 0; accI[ff][1] = 0;
    }
#pragma unroll 8
    for (int k = 0; k < 64; k++) {
        float4 wc = *(const float4*)&sWc[k * FWF + f0];
        float4 ws = *(const float4*)&sWs[k * FWF + f0];
        ulonglong2 vp = *(const ulonglong2*)&sV[k * 68 + tube0];
        const float* wcp = &wc.x;
        const float* wsp = &ws.x;
#pragma unroll
        for (int ff = 0; ff < 4; ff++) {
            ull bc = bcast2(wcp[ff]);
            ull bs = bcast2(wsp[ff]);
            ffma2(accR[ff][0], vp.x, bc);
            ffma2(accR[ff][1], vp.y, bc);
            ffma2(accI[ff][0], vp.x, bs);
            ffma2(accI[ff][1], vp.y, bs);
        }
    }

    size_t obase = (size_t)b * FDIM * SLICE + rc0;
#pragma unroll
    for (int ff = 0; ff < 4; ff++) {
        int f = f0 + ff;
        float2 r0 = unpack2(accR[ff][0]), r1 = unpack2(accR[ff][1]);
        float2 i0 = unpack2(accI[ff][0]), i1 = unpack2(accI[ff][1]);
        *(float4*)&outr[obase + (size_t)f * SLICE + tube0] =
            make_float4(r0.x, r0.y, r1.x, r1.y);
        *(float4*)&outi[obase + (size_t)f * SLICE + tube0] =
            make_float4(i0.x, i0.y, i1.x, i1.y);
    }
    if (tid < 64) {
        float re = 0.f;
#pragma unroll 16
        for (int t = 0; t < 64; t += 2)
            re += sV[t * 68 + tid] - sV[(t + 1) * 68 + tid];
        outr[obase + (size_t)32 * SLICE + tid] = re;
        outi[obase + (size_t)32 * SLICE + tid] = 0.f;
    }
}

// ---------------- forward rDFT (B, transposed out): tubes -> [b][f][n][j] --
__global__ void __launch_bounds__(128) dftf_T(const float* __restrict__ x,
                                              float* __restrict__ outr,
                                              float* __restrict__ outi) {
    __shared__ float sV[64 * 68];
    __shared__ float sWc[64 * FWF];
    __shared__ float sWs[64 * FWF];
    int tid = threadIdx.x;
    int blk = blockIdx.x;
    int b = blk >> 10;
    int n = (blk >> 2) & 255;
    int jg = blk & 3;

    {
        const float* srcbase = x + ((size_t)((b * 256 + jg * 64) * 256 + n)) * 64;
#pragma unroll
        for (int it = 0; it < 8; it++) {
            int flat = tid + it * 128;
            int tube = flat >> 4;               // local j
            int t0 = (flat & 15) * 4;
            float4 v = *(const float4*)(srcbase + (size_t)tube * 16384 + t0);
            sV[(t0 + 0) * 68 + tube] = v.x;
            sV[(t0 + 1) * 68 + tube] = v.y;
            sV[(t0 + 2) * 68 + tube] = v.z;
            sV[(t0 + 3) * 68 + tube] = v.w;
        }
    }
    for (int idx = tid; idx < 64 * FWF; idx += 128) {
        sWc[idx] = g_cosT[idx];
        sWs[idx] = g_sinT[idx];
    }
    __syncthreads();

    int ty = tid >> 4;
    int tx = tid & 15;
    int f0 = ty * 4, tube0 = tx * 4;

    ull accR[4][2], accI[4][2];
#pragma unroll
    for (int ff = 0; ff < 4; ff++) {
        accR[ff][0] = 0; accR[ff][1] = 0; accI[ff][0] = 0; accI[ff][1] = 0;
    }
#pragma unroll 8
    for (int k = 0; k < 64; k++) {
        float4 wc = *(const float4*)&sWc[k * FWF + f0];
        float4 ws = *(const float4*)&sWs[k * FWF + f0];
        ulonglong2 vp = *(const ulonglong2*)&sV[k * 68 + tube0];
        const float* wcp = &wc.x;
        const float* wsp = &ws.x;
#pragma unroll
        for (int ff = 0; ff < 4; ff++) {
            ull bc = bcast2(wcp[ff]);
            ull bs = bcast2(wsp[ff]);
            ffma2(accR[ff][0], vp.x, bc);
            ffma2(accR[ff][1], vp.y, bc);
            ffma2(accI[ff][0], vp.x, bs);
            ffma2(accI[ff][1], vp.y, bs);
        }
    }

    size_t obase = (size_t)b * FDIM * SLICE + (size_t)n * NDIM + jg * 64;
#pragma unroll
    for (int ff = 0; ff < 4; ff++) {
        int f = f0 + ff;
        float2 r0 = unpack2(accR[ff][0]), r1 = unpack2(accR[ff][1]);
        float2 i0 = unpack2(accI[ff][0]), i1 = unpack2(accI[ff][1]);
        *(float4*)&outr[obase + (size_t)f * SLICE + tube0] =
            make_float4(r0.x, r0.y, r1.x, r1.y);
        *(float4*)&outi[obase + (size_t)f * SLICE + tube0] =
            make_float4(i0.x, i0.y, i1.x, i1.y);
    }
    if (tid < 64) {
        float re = 0.f;
#pragma unroll 16
        for (int t = 0; t < 64; t += 2)
            re += sV[t * 68 + tid] - sV[(t + 1) * 68 + tid];
        outr[obase + (size_t)32 * SLICE + tid] = re;
        outi[obase + (size_t)32 * SLICE + tid] = 0.f;
    }
}

// ---------------- tf32 mma.sync complex GEMM per (b,f) ---------------------
// CTA tile M=128 x N=64, 8 warps (4 m x 2 n), warp tile 32x32 (2x4 m16n8k8).
// K chunked at 32 through smem (pitch 36 words: conflict-free frag LDS,
// 16B-aligned staging). Cr = Ar*Br + (-Ai)*Bi (sign-flip frag), Ci = Ar*Bi + Ai*Br.
#define KP 36
#define SM_A_WORDS (128 * KP)
#define SM_B_WORDS (64 * KP)
#define SMEM_MMA ((2 * SM_A_WORDS + 2 * SM_B_WORDS) * 4)  // 55296 B

__global__ void __launch_bounds__(256, 2) cgemm_mma(const float* __restrict__ Ar,
                                                    const float* __restrict__ Ai,
                                                    const float* __restrict__ Br,
                                                    const float* __restrict__ Bi,
                                                    float* __restrict__ Cr,
                                                    float* __restrict__ Ci) {
    extern __shared__ uint32_t smw[];
    uint32_t* sAr = smw;
    uint32_t* sAi = smw + SM_A_WORDS;
    uint32_t* sBr = smw + 2 * SM_A_WORDS;
    uint32_t* sBi = smw + 2 * SM_A_WORDS + SM_B_WORDS;
    size_t off = (size_t)blockIdx.z * SLICE;
    int i0 = blockIdx.y * 128, n0 = blockIdx.x * 64;
    int tid = threadIdx.x;
    int wid = tid >> 5, lane = tid & 31;
    int wm = wid & 3;          // m block: wm*32
    int wn = wid >> 2;         // n block: wn*32
    int g = lane >> 2, tg = lane & 3;

    float cr[2][4][4], ci[2][4][4];
#pragma unroll
    for (int mt = 0; mt < 2; mt++)
#pragma unroll
        for (int nt = 0; nt < 4; nt++)
#pragma unroll
            for (int e = 0; e < 4; e++) { cr[mt][nt][e] = 0.f; ci[mt][nt][e] = 0.f; }

    for (int c = 0; c < 8; c++) {
        int k0 = c * 32;
        // stage A planes: 128 rows x 32 k (1024 float4 per plane)
#pragma unroll
        for (int it = 0; it < 4; it++) {
            int idx = tid + it * 256;
            int m = idx >> 3, kq = (idx & 7) * 4;
            size_t gg = off + (size_t)(i0 + m) * NDIM + k0 + kq;
            float4 va = *(const float4*)&Ar[gg];
            float4 vb = *(const float4*)&Ai[gg];
            *(uint4*)&sAr[m * KP + kq] =
                make_uint4(f2tf32(va.x), f2tf32(va.y), f2tf32(va.z), f2tf32(va.w));
            *(uint4*)&sAi[m * KP + kq] =
                make_uint4(f2tf32(vb.x), f2tf32(vb.y), f2tf32(vb.z), f2tf32(vb.w));
        }
        // stage B planes: 64 rows x 32 k (512 float4 per plane)
#pragma unroll
        for (int it = 0; it < 2; it++) {
            int idx = tid + it * 256;
            int n = idx >> 3, kq = (idx & 7) * 4;
            size_t gg = off + (size_t)(n0 + n) * NDIM + k0 + kq;
            float4 va = *(const float4*)&Br[gg];
            float4 vb = *(const float4*)&Bi[gg];
            *(uint4*)&sBr[n * KP + kq] =
                make_uint4(f2tf32(va.x), f2tf32(va.y), f2tf32(va.z), f2tf32(va.w));
            *(uint4*)&sBi[n * KP + kq] =
                make_uint4(f2tf32(vb.x), f2tf32(vb.y), f2tf32(vb.z), f2tf32(vb.w));
        }
        __syncthreads();

#pragma unroll
        for (int ks = 0; ks < 4; ks++) {
            int kk = ks * 8;
            uint32_t ar[2][4], ai[2][4], an[2][4];
#pragma unroll
            for (int mt = 0; mt < 2; mt++) {
                int r0 = wm * 32 + mt * 16;
                ar[mt][0] = sAr[(r0 + g) * KP + kk + tg];
                ar[mt][1] = sAr[(r0 + g + 8) * KP + kk + tg];
                ar[mt][2] = sAr[(r0 + g) * KP + kk + tg + 4];
                ar[mt][3] = sAr[(r0 + g + 8) * KP + kk + tg + 4];
                ai[mt][0] = sAi[(r0 + g) * KP + kk + tg];
                ai[mt][1] = sAi[(r0 + g + 8) * KP + kk + tg];
                ai[mt][2] = sAi[(r0 + g) * KP + kk + tg + 4];
                ai[mt][3] = sAi[(r0 + g + 8) * KP + kk + tg + 4];
#pragma unroll
                for (int e = 0; e < 4; e++) an[mt][e] = ai[mt][e] ^ 0x80000000u;
            }
            uint32_t br[4][2], bi[4][2];
#pragma unroll
            for (int nt = 0; nt < 4; nt++) {
                int cb = wn * 32 + nt * 8;
                br[nt][0] = sBr[(cb + g) * KP + kk + tg];
                br[nt][1] = sBr[(cb + g) * KP + kk + tg + 4];
                bi[nt][0] = sBi[(cb + g) * KP + kk + tg];
                bi[nt][1] = sBi[(cb + g) * KP + kk + tg + 4];
            }
#pragma unroll
            for (int mt = 0; mt < 2; mt++)
#pragma unroll
                for (int nt = 0; nt < 4; nt++) {
                    mma16n8k8(cr[mt][nt], ar[mt], br[nt]);
                    mma16n8k8(cr[mt][nt], an[mt], bi[nt]);
                    mma16n8k8(ci[mt][nt], ar[mt], bi[nt]);
                    mma16n8k8(ci[mt][nt], ai[mt], br[nt]);
                }
        }
        __syncthreads();
    }

    // epilogue: c0/c1 -> (row g, cols 2tg,2tg+1); c2/c3 -> (row g+8)
#pragma unroll
    for (int mt = 0; mt < 2; mt++) {
#pragma unroll
        for (int nt = 0; nt < 4; nt++) {
            int r = i0 + wm * 32 + mt * 16 + g;
            int col = n0 + wn * 32 + nt * 8 + 2 * tg;
            size_t p0 = off + (size_t)r * NDIM + col;
            size_t p1 = off + (size_t)(r + 8) * NDIM + col;
            *(float2*)&Cr[p0] = make_float2(cr[mt][nt][0], cr[mt][nt][1]);
            *(float2*)&Cr[p1] = make_float2(cr[mt][nt][2], cr[mt][nt][3]);
            *(float2*)&Ci[p0] = make_float2(ci[mt][nt][0], ci[mt][nt][1]);
            *(float2*)&Ci[p1] = make_float2(ci[mt][nt][2], ci[mt][nt][3]);
        }
    }
}

// ---------------- inverse rDFT as GEMM: C[tube,t] = sum_f cr*Tc + ci*Ts ----
__global__ void __launch_bounds__(128) dfti(const float* __restrict__ cfr_g,
                                            const float* __restrict__ cfi_g,
                                            float* __restrict__ out) {
    __shared__ float sCr[FDIM * 64];
    __shared__ float sCi[FDIM * 64];
    __shared__ float sTc[FDIM * 64];
    __shared__ float sTs[FDIM * 64];
    int tid = threadIdx.x;
    size_t tube_base = (size_t)blockIdx.x * 64;
    int b = (int)(tube_base >> 16);
    int rc0 = (int)(tube_base & 65535);
    size_t gbase = (size_t)b * FDIM * SLICE + rc0;

    for (int idx = tid; idx < FDIM * 64; idx += 128) {
        int f = idx >> 6, n = idx & 63;
        size_t g = gbase + (size_t)f * SLICE + n;
        sCr[idx] = cfr_g[g];
        sCi[idx] = cfi_g[g];
        sTc[idx] = g_icosF[idx];
        sTs[idx] = g_isinF[idx];
    }
    __syncthreads();

    int ty = tid >> 3;
    int tx = tid & 7;
    int t0 = ty * 4, tube0 = tx * 8;

    ull acc[4][4];
#pragma unroll
    for (int tt = 0; tt < 4; tt++)
#pragma unroll
        for (int p = 0; p < 4; p++) acc[tt][p] = 0ull;

    for (int f = 0; f < FDIM; f++) {
        float4 tc = *(const float4*)&sTc[f * 64 + t0];
        float4 tsv = *(const float4*)&sTs[f * 64 + t0];
        ulonglong2 c01 = *(const ulonglong2*)&sCr[f * 64 + tube0];
        ulonglong2 c23 = *(const ulonglong2*)&sCr[f * 64 + tube0 + 4];
        ulonglong2 i01 = *(const ulonglong2*)&sCi[f * 64 + tube0];
        ulonglong2 i23 = *(const ulonglong2*)&sCi[f * 64 + tube0 + 4];
        ull crp[4] = {c01.x, c01.y, c23.x, c23.y};
        ull cip[4] = {i01.x, i01.y, i23.x, i23.y};
        const float* tcp = &tc.x;
        const float* tsp = &tsv.x;
#pragma unroll
        for (int tt = 0; tt < 4; tt++) {
            ull bc = bcast2(tcp[tt]);
            ull bs = bcast2(tsp[tt]);
#pragma unroll
            for (int p = 0; p < 4; p++) {
                ffma2(acc[tt][p], crp[p], bc);
                ffma2(acc[tt][p], cip[p], bs);
            }
        }
    }

    float* dst = out + (tube_base + tube0) * TDIM + t0;
#pragma unroll
    for (int p = 0; p < 4; p++) {
        float2 v0 = unpack2(acc[0][p]);
        float2 v1 = unpack2(acc[1][p]);
        float2 v2 = unpack2(acc[2][p]);
        float2 v3 = unpack2(acc[3][p]);
        *(float4*)&dst[(2 * p) * TDIM]     = make_float4(v0.x, v1.x, v2.x, v3.x);
        *(float4*)&dst[(2 * p + 1) * TDIM] = make_float4(v0.y, v1.y, v2.y, v3.y);
    }
}

// ---------------------------------------------------------------------------
extern "C" void kernel_launch(void* const* d_in, const int* in_sizes, int n_in,
                              void* d_out, int out_size) {
    (void)in_sizes; (void)n_in; (void)out_size;
    const float* A = (const float*)d_in[0];
    const float* B = (const float*)d_in[1];
    float* C = (float*)d_out;

    float *afr, *afi, *bfr, *bfi, *cfr, *cfi;
    cudaGetSymbolAddress((void**)&afr, g_Afr);
    cudaGetSymbolAddress((void**)&afi, g_Afi);
    cudaGetSymbolAddress((void**)&bfr, g_Bfr);
    cudaGetSymbolAddress((void**)&bfi, g_Bfi);
    cudaGetSymbolAddress((void**)&cfr, g_Cfr);
    cudaGetSymbolAddress((void**)&cfi, g_Cfi);

    static int smem_set = 0;
    if (!smem_set) {
        cudaFuncSetAttribute(cgemm_mma, cudaFuncAttributeMaxDynamicSharedMemorySize,
                             SMEM_MMA);
        smem_set = 1;
    }

    init_twiddles<<<10, 256>>>();
    dftf<<<TOTAL_TUBES / 64, 128>>>(A, afr, afi);
    dftf_T<<<TOTAL_TUBES / 64, 128>>>(B, bfr, bfi);
    cgemm_mma<<<dim3(NDIM / 64, NDIM / 128, NBF), 256, SMEM_MMA>>>(afr, afi, bfr, bfi,
                                                                   cfr, cfi);
    dfti<<<TOTAL_TUBES / 64, 128>>>(cfr, cfi, C);
}

// round 12
// speedup vs baseline: 2.7201x; 1.1384x over previous
#include <cuda_runtime.h>
#include <math.h>
#include <stdint.h>

#define BATCH 8
#define NDIM 256
#define TDIM 64
#define FDIM 33                    // rFFT bins for length-64 real input
#define SLICE (NDIM * NDIM)        // 65536
#define NBF (BATCH * FDIM)         // 264
#define TOTAL_TUBES (BATCH * NDIM * NDIM)  // 524288
#define PLANE_ELEMS ((size_t)NBF * SLICE)

// ---------------- tf32 mma.sync helpers (baseline PTX, sm_80+) -------------
__device__ __forceinline__ uint32_t f2tf32(float x) {
    uint32_t r; asm("cvt.rna.tf32.f32 %0, %1;" : "=r"(r) : "f"(x)); return r;
}
__device__ __forceinline__ void mma16n8k8(float* c, const uint32_t* a, const uint32_t* b) {
    asm volatile(
        "mma.sync.aligned.m16n8k8.row.col.f32.tf32.tf32.f32 "
        "{%0,%1,%2,%3}, {%4,%5,%6,%7}, {%8,%9}, {%0,%1,%2,%3};"
        : "+f"(c[0]), "+f"(c[1]), "+f"(c[2]), "+f"(c[3])
        : "r"(a[0]), "r"(a[1]), "r"(a[2]), "r"(a[3]), "r"(b[0]), "r"(b[1]));
}

// ---------------- scratch (device globals: allocation-free) ----------------
__device__ float g_Afr[PLANE_ELEMS];   // [b*f][i][k]
__device__ float g_Afi[PLANE_ELEMS];
__device__ float g_Bfr[PLANE_ELEMS];   // [b*f][n][j]  (transposed)
__device__ float g_Bfi[PLANE_ELEMS];
__device__ float g_Cfr[PLANE_ELEMS];   // [b*f][i][n]
__device__ float g_Cfi[PLANE_ELEMS];

// twiddle tables, pre-converted to tf32 bit patterns
__device__ uint32_t g_fwdW[80 * 64];   // rows 0-39: cos(f,t) (f<33 else 0); 40-79: -sin
__device__ uint32_t g_invW[64 * 76];   // [t][k]: k<36: w*cos/64; 36..71: -w*sin/64; else 0

__global__ void init_twiddles() {
    int idx = blockIdx.x * blockDim.x + threadIdx.x;
    if (idx < 80 * 64) {
        int n = idx >> 6, t = idx & 63;
        float v = 0.f;
        int f = (n < 40) ? n : n - 40;
        if (f < FDIM) {
            int r = (f * t) & 63;
            double s, c;
            sincospi(2.0 * (double)r / 64.0, &s, &c);
            v = (n < 40) ? (float)c : (float)(-s);
        }
        g_fwdW[idx] = f2tf32(v);
    }
    if (idx < 64 * 76) {
        int t = idx / 76, k = idx % 76;
        float v = 0.f;
        if (k < 72) {
            int f = (k < 36) ? k : k - 36;
            if (f < FDIM) {
                int r = (f * t) & 63;
                double s, c;
                sincospi(2.0 * (double)r / 64.0, &s, &c);
                double w = (f == 0 || f == 32) ? 1.0 : 2.0;
                v = (k < 36) ? (float)(w * c / 64.0) : (float)(-w * s / 64.0);
            }
        }
        g_invW[idx] = f2tf32(v);
    }
}

// ---------------- forward rDFT via mma: 128 tubes/CTA ----------------------
// C[tube, f'] = V[tube, t] * W[f', t]^T ; f' 0-39 = Re bins, 40-79 = Im bins.
// TRANS=false: A input, contiguous tubes. TRANS=true: B input, j-gather at fixed n.
#define FWD_AP 68
#define FWD_SMEM ((128 * FWD_AP + 80 * FWD_AP) * 4)   // 56576 B (overlay: 80*132*4)

template <bool TRANS>
__global__ void __launch_bounds__(256, 2) dft_fwd_mma(const float* __restrict__ x,
                                                      float* __restrict__ outr,
                                                      float* __restrict__ outi) {
    extern __shared__ uint32_t sm[];
    uint32_t* sA = sm;                    // [128][68]
    uint32_t* sB = sm + 128 * FWD_AP;     // [80][68]
    float* sOut = (float*)sm;             // overlay [80][132] after MMA
    int tid = threadIdx.x;
    int blk = blockIdx.x;

    size_t obase;
    const float* src;
    size_t tstr;
    if (!TRANS) {
        size_t tube_base = (size_t)blk * 128;
        obase = (size_t)(tube_base >> 16) * FDIM * SLICE + (tube_base & 65535);
        src = x + tube_base * TDIM;
        tstr = TDIM;
    } else {
        int b = blk >> 9;
        int n = (blk >> 1) & 255;
        int jg = blk & 1;
        obase = (size_t)b * FDIM * SLICE + (size_t)n * NDIM + jg * 128;
        src = x + ((size_t)((b * 256 + jg * 128) * 256 + n)) * TDIM;
        tstr = 16384;
    }

    // stage A: 128 tubes x 64 t, tf32
#pragma unroll
    for (int it = 0; it < 8; it++) {
        int flat = tid + it * 256;
        int tube = flat >> 4;
        int q = (flat & 15) * 4;
        float4 v = *(const float4*)(src + (size_t)tube * tstr + q);
        *(uint4*)&sA[tube * FWD_AP + q] =
            make_uint4(f2tf32(v.x), f2tf32(v.y), f2tf32(v.z), f2tf32(v.w));
    }
    // stage B: twiddle table (already tf32 bits)
    for (int idx = tid; idx < 80 * 64; idx += 256)
        sB[(idx >> 6) * FWD_AP + (idx & 63)] = g_fwdW[idx];
    __syncthreads();

    int wid = tid >> 5, lane = tid & 31;
    int wm = wid & 3, wn = wid >> 2;      // warp tile 32m x 40n
    int g = lane >> 2, tg = lane & 3;

    float acc[2][5][4];
#pragma unroll
    for (int mt = 0; mt < 2; mt++)
#pragma unroll
        for (int nt = 0; nt < 5; nt++)
#pragma unroll
            for (int e = 0; e < 4; e++) acc[mt][nt][e] = 0.f;

#pragma unroll
    for (int ks = 0; ks < 8; ks++) {
        int kk = ks * 8;
        uint32_t af[2][4];
#pragma unroll
        for (int mt = 0; mt < 2; mt++) {
            int r0 = wm * 32 + mt * 16;
            af[mt][0] = sA[(r0 + g) * FWD_AP + kk + tg];
            af[mt][1] = sA[(r0 + g + 8) * FWD_AP + kk + tg];
            af[mt][2] = sA[(r0 + g) * FWD_AP + kk + tg + 4];
            af[mt][3] = sA[(r0 + g + 8) * FWD_AP + kk + tg + 4];
        }
        uint32_t bf[5][2];
#pragma unroll
        for (int nt = 0; nt < 5; nt++) {
            int cb = wn * 40 + nt * 8;
            bf[nt][0] = sB[(cb + g) * FWD_AP + kk + tg];
            bf[nt][1] = sB[(cb + g) * FWD_AP + kk + tg + 4];
        }
#pragma unroll
        for (int mt = 0; mt < 2; mt++)
#pragma unroll
            for (int nt = 0; nt < 5; nt++)
                mma16n8k8(acc[mt][nt], af[mt], bf[nt]);
    }
    __syncthreads();

    // transpose through smem: sOut[col][tube], pitch 132
#pragma unroll
    for (int mt = 0; mt < 2; mt++)
#pragma unroll
        for (int nt = 0; nt < 5; nt++) {
            int r = wm * 32 + mt * 16 + g;
            int c = wn * 40 + nt * 8 + 2 * tg;
            sOut[c * 132 + r] = acc[mt][nt][0];
            sOut[(c + 1) * 132 + r] = acc[mt][nt][1];
            sOut[c * 132 + r + 8] = acc[mt][nt][2];
            sOut[(c + 1) * 132 + r + 8] = acc[mt][nt][3];
        }
    __syncthreads();

    // coalesced stores: 33 freq rows x 128 tubes, Re + Im
#pragma unroll
    for (int it = 0; it < 9; it++) {
        int flat = tid + it * 256;
        if (flat < 1056) {
            int f = flat >> 5, v4 = (flat & 31) * 4;
            float4 val = *(float4*)&sOut[f * 132 + v4];
            *(float4*)&outr[obase + (size_t)f * SLICE + v4] = val;
        } else if (flat < 2112) {
            int f2 = flat - 1056;
            int f = f2 >> 5, v4 = (f2 & 31) * 4;
            float4 val = *(float4*)&sOut[(40 + f) * 132 + v4];
            *(float4*)&outi[obase + (size_t)f * SLICE + v4] = val;
        }
    }
}

// ---------------- tf32 mma.sync complex GEMM per (b,f) ---------------------
#define KP 36
#define SM_A_WORDS (128 * KP)
#define SM_B_WORDS (64 * KP)
#define SMEM_MMA ((2 * SM_A_WORDS + 2 * SM_B_WORDS) * 4)  // 55296 B

__global__ void __launch_bounds__(256, 2) cgemm_mma(const float* __restrict__ Ar,
                                                    const float* __restrict__ Ai,
                                                    const float* __restrict__ Br,
                                                    const float* __restrict__ Bi,
                                                    float* __restrict__ Cr,
                                                    float* __restrict__ Ci) {
    extern __shared__ uint32_t smw[];
    uint32_t* sAr = smw;
    uint32_t* sAi = smw + SM_A_WORDS;
    uint32_t* sBr = smw + 2 * SM_A_WORDS;
    uint32_t* sBi = smw + 2 * SM_A_WORDS + SM_B_WORDS;
    size_t off = (size_t)blockIdx.z * SLICE;
    int i0 = blockIdx.y * 128, n0 = blockIdx.x * 64;
    int tid = threadIdx.x;
    int wid = tid >> 5, lane = tid & 31;
    int wm = wid & 3;
    int wn = wid >> 2;
    int g = lane >> 2, tg = lane & 3;

    float cr[2][4][4], ci[2][4][4];
#pragma unroll
    for (int mt = 0; mt < 2; mt++)
#pragma unroll
        for (int nt = 0; nt < 4; nt++)
#pragma unroll
            for (int e = 0; e < 4; e++) { cr[mt][nt][e] = 0.f; ci[mt][nt][e] = 0.f; }

    for (int c = 0; c < 8; c++) {
        int k0 = c * 32;
#pragma unroll
        for (int it = 0; it < 4; it++) {
            int idx = tid + it * 256;
            int m = idx >> 3, kq = (idx & 7) * 4;
            size_t gg = off + (size_t)(i0 + m) * NDIM + k0 + kq;
            float4 va = *(const float4*)&Ar[gg];
            float4 vb = *(const float4*)&Ai[gg];
            *(uint4*)&sAr[m * KP + kq] =
                make_uint4(f2tf32(va.x), f2tf32(va.y), f2tf32(va.z), f2tf32(va.w));
            *(uint4*)&sAi[m * KP + kq] =
                make_uint4(f2tf32(vb.x), f2tf32(vb.y), f2tf32(vb.z), f2tf32(vb.w));
        }
#pragma unroll
        for (int it = 0; it < 2; it++) {
            int idx = tid + it * 256;
            int n = idx >> 3, kq = (idx & 7) * 4;
            size_t gg = off + (size_t)(n0 + n) * NDIM + k0 + kq;
            float4 va = *(const float4*)&Br[gg];
            float4 vb = *(const float4*)&Bi[gg];
            *(uint4*)&sBr[n * KP + kq] =
                make_uint4(f2tf32(va.x), f2tf32(va.y), f2tf32(va.z), f2tf32(va.w));
            *(uint4*)&sBi[n * KP + kq] =
                make_uint4(f2tf32(vb.x), f2tf32(vb.y), f2tf32(vb.z), f2tf32(vb.w));
        }
        __syncthreads();

#pragma unroll
        for (int ks = 0; ks < 4; ks++) {
            int kk = ks * 8;
            uint32_t ar[2][4], ai[2][4], an[2][4];
#pragma unroll
            for (int mt = 0; mt < 2; mt++) {
                int r0 = wm * 32 + mt * 16;
                ar[mt][0] = sAr[(r0 + g) * KP + kk + tg];
                ar[mt][1] = sAr[(r0 + g + 8) * KP + kk + tg];
                ar[mt][2] = sAr[(r0 + g) * KP + kk + tg + 4];
                ar[mt][3] = sAr[(r0 + g + 8) * KP + kk + tg + 4];
                ai[mt][0] = sAi[(r0 + g) * KP + kk + tg];
                ai[mt][1] = sAi[(r0 + g + 8) * KP + kk + tg];
                ai[mt][2] = sAi[(r0 + g) * KP + kk + tg + 4];
                ai[mt][3] = sAi[(r0 + g + 8) * KP + kk + tg + 4];
#pragma unroll
                for (int e = 0; e < 4; e++) an[mt][e] = ai[mt][e] ^ 0x80000000u;
            }
            uint32_t br[4][2], bi[4][2];
#pragma unroll
            for (int nt = 0; nt < 4; nt++) {
                int cb = wn * 32 + nt * 8;
                br[nt][0] = sBr[(cb + g) * KP + kk + tg];
                br[nt][1] = sBr[(cb + g) * KP + kk + tg + 4];
                bi[nt][0] = sBi[(cb + g) * KP + kk + tg];
                bi[nt][1] = sBi[(cb + g) * KP + kk + tg + 4];
            }
#pragma unroll
            for (int mt = 0; mt < 2; mt++)
#pragma unroll
                for (int nt = 0; nt < 4; nt++) {
                    mma16n8k8(cr[mt][nt], ar[mt], br[nt]);
                    mma16n8k8(cr[mt][nt], an[mt], bi[nt]);
                    mma16n8k8(ci[mt][nt], ar[mt], bi[nt]);
                    mma16n8k8(ci[mt][nt], ai[mt], br[nt]);
                }
        }
        __syncthreads();
    }

#pragma unroll
    for (int mt = 0; mt < 2; mt++) {
#pragma unroll
        for (int nt = 0; nt < 4; nt++) {
            int r = i0 + wm * 32 + mt * 16 + g;
            int col = n0 + wn * 32 + nt * 8 + 2 * tg;
            size_t p0 = off + (size_t)r * NDIM + col;
            size_t p1 = off + (size_t)(r + 8) * NDIM + col;
            *(float2*)&Cr[p0] = make_float2(cr[mt][nt][0], cr[mt][nt][1]);
            *(float2*)&Cr[p1] = make_float2(cr[mt][nt][2], cr[mt][nt][3]);
            *(float2*)&Ci[p0] = make_float2(ci[mt][nt][0], ci[mt][nt][1]);
            *(float2*)&Ci[p1] = make_float2(ci[mt][nt][2], ci[mt][nt][3]);
        }
    }
}

// ---------------- inverse rDFT via mma: 128 tubes/CTA ----------------------
// C[tube, t] = [cr | ci][tube, k] * invW[t, k]^T,  K = 72 (36+36 padded)
#define INV_AP 76
#define INV_SMEM ((128 * INV_AP + 64 * INV_AP) * 4)   // 58368 B

__global__ void __launch_bounds__(256, 2) dft_inv_mma(const float* __restrict__ cfr,
                                                      const float* __restrict__ cfi,
                                                      float* __restrict__ out) {
    extern __shared__ uint32_t sm[];
    uint32_t* sA = sm;                    // [128][76]
    uint32_t* sB = sm + 128 * INV_AP;     // [64][76]
    int tid = threadIdx.x;
    size_t tube_base = (size_t)blockIdx.x * 128;
    int b = (int)(tube_base >> 16);
    int rc0 = (int)(tube_base & 65535);
    size_t gbase = (size_t)b * FDIM * SLICE + rc0;

    // zero pad cols 33-35, 69-71
    for (int idx = tid; idx < 128 * 6; idx += 256) {
        int tube = idx / 6, c = idx % 6;
        int col = (c < 3) ? (33 + c) : (66 + c);
        sA[tube * INV_AP + col] = 0;
    }
    // stage spectrum (transposed scatter, tf32)
    for (int idx = tid; idx < FDIM * 128; idx += 256) {
        int f = idx >> 7, tube = idx & 127;
        size_t g = gbase + (size_t)f * SLICE + tube;
        sA[tube * INV_AP + f] = f2tf32(cfr[g]);
        sA[tube * INV_AP + 36 + f] = f2tf32(cfi[g]);
    }
    for (int idx = tid; idx < 64 * INV_AP; idx += 256)
        sB[idx] = g_invW[idx];
    __syncthreads();

    int wid = tid >> 5, lane = tid & 31;
    int wm = wid & 3, wn = wid >> 2;      // warp tile 32m x 32n
    int g = lane >> 2, tg = lane & 3;

    float acc[2][4][4];
#pragma unroll
    for (int mt = 0; mt < 2; mt++)
#pragma unroll
        for (int nt = 0; nt < 4; nt++)
#pragma unroll
            for (int e = 0; e < 4; e++) acc[mt][nt][e] = 0.f;

#pragma unroll
    for (int ks = 0; ks < 9; ks++) {
        int kk = ks * 8;
        uint32_t af[2][4];
#pragma unroll
        for (int mt = 0; mt < 2; mt++) {
            int r0 = wm * 32 + mt * 16;
            af[mt][0] = sA[(r0 + g) * INV_AP + kk + tg];
            af[mt][1] = sA[(r0 + g + 8) * INV_AP + kk + tg];
            af[mt][2] = sA[(r0 + g) * INV_AP + kk + tg + 4];
            af[mt][3] = sA[(r0 + g + 8) * INV_AP + kk + tg + 4];
        }
        uint32_t bf[4][2];
#pragma unroll
        for (int nt = 0; nt < 4; nt++) {
            int cb = wn * 32 + nt * 8;
            bf[nt][0] = sB[(cb + g) * INV_AP + kk + tg];
            bf[nt][1] = sB[(cb + g) * INV_AP + kk + tg + 4];
        }
#pragma unroll
        for (int mt = 0; mt < 2; mt++)
#pragma unroll
            for (int nt = 0; nt < 4; nt++)
                mma16n8k8(acc[mt][nt], af[mt], bf[nt]);
    }

    // direct stores: out[(tube)*64 + t] is the native output layout
#pragma unroll
    for (int mt = 0; mt < 2; mt++)
#pragma unroll
        for (int nt = 0; nt < 4; nt++) {
            int r = wm * 32 + mt * 16 + g;
            int c = wn * 32 + nt * 8 + 2 * tg;
            float* p = out + (tube_base + r) * TDIM + c;
            *(float2*)p = make_float2(acc[mt][nt][0], acc[mt][nt][1]);
            *(float2*)(p + 8 * TDIM) = make_float2(acc[mt][nt][2], acc[mt][nt][3]);
        }
}

// ---------------------------------------------------------------------------
extern "C" void kernel_launch(void* const* d_in, const int* in_sizes, int n_in,
                              void* d_out, int out_size) {
    (void)in_sizes; (void)n_in; (void)out_size;
    const float* A = (const float*)d_in[0];
    const float* B = (const float*)d_in[1];
    float* C = (float*)d_out;

    float *afr, *afi, *bfr, *bfi, *cfr, *cfi;
    cudaGetSymbolAddress((void**)&afr, g_Afr);
    cudaGetSymbolAddress((void**)&afi, g_Afi);
    cudaGetSymbolAddress((void**)&bfr, g_Bfr);
    cudaGetSymbolAddress((void**)&bfi, g_Bfi);
    cudaGetSymbolAddress((void**)&cfr, g_Cfr);
    cudaGetSymbolAddress((void**)&cfi, g_Cfi);

    static int attr_set = 0;
    if (!attr_set) {
        cudaFuncSetAttribute(cgemm_mma, cudaFuncAttributeMaxDynamicSharedMemorySize,
                             SMEM_MMA);
        cudaFuncSetAttribute(dft_fwd_mma<false>,
                             cudaFuncAttributeMaxDynamicSharedMemorySize, FWD_SMEM);
        cudaFuncSetAttribute(dft_fwd_mma<true>,
                             cudaFuncAttributeMaxDynamicSharedMemorySize, FWD_SMEM);
        cudaFuncSetAttribute(dft_inv_mma,
                             cudaFuncAttributeMaxDynamicSharedMemorySize, INV_SMEM);
        attr_set = 1;
    }

    init_twiddles<<<20, 256>>>();
    dft_fwd_mma<false><<<TOTAL_TUBES / 128, 256, FWD_SMEM>>>(A, afr, afi);
    dft_fwd_mma<true><<<TOTAL_TUBES / 128, 256, FWD_SMEM>>>(B, bfr, bfi);
    cgemm_mma<<<dim3(NDIM / 64, NDIM / 128, NBF), 256, SMEM_MMA>>>(afr, afi, bfr, bfi,
                                                                   cfr, cfi);
    dft_inv_mma<<<TOTAL_TUBES / 128, 256, INV_SMEM>>>(cfr, cfi, C);
}